// round 6
// baseline (speedup 1.0000x reference)
#include <cuda_runtime.h>
#include <cuda_bf16.h>
#include <cstdint>

// Problem constants
#define B_   4
#define C_   256
#define DQK_ 32
#define N_   4096   // 64*64

typedef uint32_t u32;

// ---------------- scratch (no allocation allowed -> device globals) ----------
__device__ __nv_bfloat16 g_q[(size_t)B_ * N_ * DQK_];   // [B][N][32], Q pre-scaled by log2(e)
__device__ __nv_bfloat16 g_k[(size_t)B_ * N_ * DQK_];   // [B][N][32]
__device__ __nv_bfloat16 g_v[(size_t)B_ * C_ * N_];     // [B][C][N] channel-major
__device__ __nv_bfloat16 g_xT[(size_t)B_ * N_ * C_];    // [B][N][C]  x transposed, bf16
__device__ __nv_bfloat16 g_wcat[320 * 256];             // [Wq*log2e; Wk; Wv]
__device__ float         g_bcat[320];                   // [bq*log2e; bk; bv]

// ---------------- helpers ------------------------------------------------------
__device__ __forceinline__ u32 pack_bf16x2(float lo, float hi) {
    u32 d;
    asm("cvt.rn.bf16x2.f32 %0, %1, %2;" : "=r"(d) : "f"(hi), "f"(lo));
    return d;
}
__device__ __forceinline__ u32 smem_u32(const void* p) {
    u32 a;
    asm("{ .reg .u64 t; cvta.to.shared.u64 t, %1; cvt.u32.u64 %0, t; }" : "=r"(a) : "l"(p));
    return a;
}
__device__ __forceinline__ void ldm_x4(u32 addr, u32& r0, u32& r1, u32& r2, u32& r3) {
    asm volatile("ldmatrix.sync.aligned.m8n8.x4.shared.b16 {%0,%1,%2,%3}, [%4];"
                 : "=r"(r0), "=r"(r1), "=r"(r2), "=r"(r3) : "r"(addr));
}
__device__ __forceinline__ void mma_bf16(float* d, const u32* a, const u32* b) {
    asm volatile(
        "mma.sync.aligned.m16n8k16.row.col.f32.bf16.bf16.f32 "
        "{%0,%1,%2,%3},{%4,%5,%6,%7},{%8,%9},{%0,%1,%2,%3};"
        : "+f"(d[0]), "+f"(d[1]), "+f"(d[2]), "+f"(d[3])
        : "r"(a[0]), "r"(a[1]), "r"(a[2]), "r"(a[3]), "r"(b[0]), "r"(b[1]));
}
__device__ __forceinline__ void cpa16(u32 dst, const void* src) {
    asm volatile("cp.async.cg.shared.global [%0], [%1], 16;" :: "r"(dst), "l"(src));
}
#define CP_COMMIT  asm volatile("cp.async.commit_group;")
#define CP_WAIT0   asm volatile("cp.async.wait_group 0;")
#define CP_WAIT1   asm volatile("cp.async.wait_group 1;")

__device__ __forceinline__ u32 swz(u32 off) { return off ^ ((off >> 3) & 0x70); }

#define L2E 1.44269504088896f

// =============================================================================
// Kernel 0a: weight stack + bf16 convert. grid(320), block(256).
// =============================================================================
__global__ void wconv(const float* __restrict__ Wq, const float* __restrict__ bq,
                      const float* __restrict__ Wk, const float* __restrict__ bk,
                      const float* __restrict__ Wv, const float* __restrict__ bv)
{
    int j = blockIdx.x, c = threadIdx.x;
    const float* src;
    float s = 1.0f, bias;
    if (j < 32)       { src = Wq + j * 256;        s = L2E; bias = bq[j] * L2E; }
    else if (j < 64)  { src = Wk + (j - 32) * 256;          bias = bk[j - 32];  }
    else              { src = Wv + (j - 64) * 256;          bias = bv[j - 64];  }
    g_wcat[j * 256 + c] = __float2bfloat16(src[c] * s);
    if (c == 0) g_bcat[j] = bias;
}

// =============================================================================
// Kernel 0b: x [B][C][N] f32 -> g_xT [B][N][C] bf16. grid(64,4,4), block(256).
// =============================================================================
__global__ __launch_bounds__(256) void xT_kernel(const float* __restrict__ x)
{
    __shared__ float T[64][65];
    const int tid = threadIdx.x;
    const int n0 = blockIdx.x * 64, c0 = blockIdx.y * 64, b = blockIdx.z;

    {
        int cr = tid >> 2, q = tid & 3;
        const float4* src = (const float4*)(x + ((size_t)(b * C_ + c0 + cr)) * N_ + n0 + q * 16);
#pragma unroll
        for (int i = 0; i < 4; ++i) {
            float4 v = src[i];
            int nn = q * 16 + i * 4;
            T[cr][nn] = v.x; T[cr][nn + 1] = v.y; T[cr][nn + 2] = v.z; T[cr][nn + 3] = v.w;
        }
    }
    __syncthreads();

    u32* dst = (u32*)g_xT;
#pragma unroll
    for (int i = 0; i < 8; ++i) {
        int idx = tid * 8 + i;
        int n = idx >> 5, cp = idx & 31;
        u32 v = pack_bf16x2(T[2 * cp][n], T[2 * cp + 1][n]);
        dst[((size_t)(b * N_ + n0 + n)) * 128 + (c0 >> 1) + cp] = v;
    }
}

// =============================================================================
// Kernel 1: projection GEMM on tensor cores (unchanged from round 5).
// =============================================================================
#define WT_OFF 1024
#define XT_OFF 17408
#define SMEM_P 50176

__global__ __launch_bounds__(128, 4)
void proj_gemm()
{
    extern __shared__ char sm[];
    const u32 sb = smem_u32(sm);
    float* bs = (float*)sm;
    const int tid = threadIdx.x;
    const int w = tid >> 5, lane = tid & 31;
    const int gid = lane >> 2, qid = lane & 3;
    const int n0 = blockIdx.x * 128;
    const int z  = blockIdx.y;
    const int b  = blockIdx.z;
    const bool qk = (z == 0);
    const int jbase = qk ? 0 : z * 64;

    if (tid < 64) bs[tid] = g_bcat[jbase + tid];

    auto load_chunk = [&](int kc) {
        int buf = kc & 1;
#pragma unroll
        for (int i = 0; i < 4; ++i) {
            int idx = i * 128 + tid;
            int r = idx >> 3, q = idx & 7;
            cpa16(sb + WT_OFF + buf * 8192 + swz(r * 128 + q * 16),
                  g_wcat + (size_t)(jbase + r) * 256 + kc * 64 + q * 8);
        }
#pragma unroll
        for (int i = 0; i < 8; ++i) {
            int idx = i * 128 + tid;
            int r = idx >> 3, q = idx & 7;
            cpa16(sb + XT_OFF + buf * 16384 + swz(r * 128 + q * 16),
                  g_xT + ((size_t)(b * N_) + n0 + r) * 256 + kc * 64 + q * 8);
        }
    };

    load_chunk(0);
    CP_COMMIT;

    float D[2][8][4];
#pragma unroll
    for (int mt = 0; mt < 2; ++mt)
#pragma unroll
        for (int nt = 0; nt < 8; ++nt)
#pragma unroll
            for (int r = 0; r < 4; ++r) D[mt][nt][r] = 0.0f;

    for (int kc = 0; kc < 4; ++kc) {
        if (kc < 3) { load_chunk(kc + 1); CP_COMMIT; CP_WAIT1; }
        else        { CP_WAIT0; }
        __syncthreads();

        const u32 wbase = sb + WT_OFF + (kc & 1) * 8192;
        const u32 xbase = sb + XT_OFF + (kc & 1) * 16384;
        const u32 abase = qk ? xbase : wbase;
        const u32 bbase = qk ? wbase : xbase;
        const int arow  = qk ? w * 32 : (w & 1) * 32;
        const int brow  = qk ? 0 : (w >> 1) * 64;

#pragma unroll
        for (int ks = 0; ks < 4; ++ks) {
            u32 aA[2][4];
#pragma unroll
            for (int mt = 0; mt < 2; ++mt) {
                int row = arow + mt * 16 + (lane & 15);
                ldm_x4(abase + swz(row * 128 + (lane >> 4) * 16 + ks * 32),
                       aA[mt][0], aA[mt][1], aA[mt][2], aA[mt][3]);
            }
#pragma unroll
            for (int ntp = 0; ntp < 4; ++ntp) {
                u32 bB[4];
                int nrow = brow + ntp * 16 + (lane & 7) + ((lane >> 4) & 1) * 8;
                ldm_x4(bbase + swz(nrow * 128 + ((lane >> 3) & 1) * 16 + ks * 32),
                       bB[0], bB[1], bB[2], bB[3]);
                mma_bf16(D[0][2 * ntp],     aA[0], bB);
                mma_bf16(D[0][2 * ntp + 1], aA[0], bB + 2);
                mma_bf16(D[1][2 * ntp],     aA[1], bB);
                mma_bf16(D[1][2 * ntp + 1], aA[1], bB + 2);
            }
        }
        __syncthreads();
    }

    if (qk) {
#pragma unroll
        for (int mt = 0; mt < 2; ++mt) {
            int n = n0 + w * 32 + mt * 16 + gid;
#pragma unroll
            for (int nt = 0; nt < 8; ++nt) {
                int j = nt * 8 + 2 * qid;
                float b0 = bs[j], b1 = bs[j + 1];
                u32 lo = pack_bf16x2(D[mt][nt][0] + b0, D[mt][nt][1] + b1);
                u32 hi = pack_bf16x2(D[mt][nt][2] + b0, D[mt][nt][3] + b1);
                int jj = j < 32 ? j : j - 32;
                u32* dst = (u32*)(j < 32 ? g_q : g_k);
                dst[((size_t)(b * N_) + n) * 16 + (jj >> 1)]       = lo;
                dst[((size_t)(b * N_) + n + 8) * 16 + (jj >> 1)]   = hi;
            }
        }
    } else {
#pragma unroll
        for (int mt = 0; mt < 2; ++mt) {
            int chl = (w & 1) * 32 + mt * 16 + gid;
            int ch  = (z - 1) * 64 + chl;
            float bv0 = bs[chl], bv1 = bs[chl + 8];
#pragma unroll
            for (int nt = 0; nt < 8; ++nt) {
                int pix = (w >> 1) * 64 + nt * 8 + 2 * qid;
                u32 lo = pack_bf16x2(D[mt][nt][0] + bv0, D[mt][nt][1] + bv0);
                u32 hi = pack_bf16x2(D[mt][nt][2] + bv1, D[mt][nt][3] + bv1);
                u32* dst = (u32*)g_v;
                dst[((size_t)(b * C_ + ch)) * 2048 + ((n0 + pix) >> 1)]     = lo;
                dst[((size_t)(b * C_ + ch + 8)) * 2048 + ((n0 + pix) >> 1)] = hi;
            }
        }
    }
}

// =============================================================================
// Kernel 2: bf16 mma.sync flash attention, PV pipelined one tile behind S.
// grid = (64, 4), 256 threads, 2 CTA/SM.
// SMEM: rowsum @0 | K 8KB @1024 | Q 2x8KB @9216 | P 2x8KB @25600 | V 2x32KB @41984
// =============================================================================
#define K_OFF     1024
#define Q_OFF     9216
#define P_OFF     25600
#define V_OFF     41984
#define SMEM_F    107520
#define STAGE_OFF 1024
#define NT        (N_ / 64)   // 64 tiles

__device__ __forceinline__ void load_qv(u32 sb, int tid, int b, int t) {
    const int buf = t & 1;
    const int n0  = t * 64;
    {
        int row = tid >> 2, ch = tid & 3;
        cpa16(sb + Q_OFF + buf * 8192 + swz(row * 128 + ch * 16),
              g_q + (size_t)(b * N_ + n0 + row) * DQK_ + ch * 8);
    }
    const __nv_bfloat16* vbase = g_v + (size_t)b * C_ * N_ + n0;
#pragma unroll
    for (int r = 0; r < 8; ++r) {
        int idx = tid + 256 * r;
        int c = idx >> 3, ch = idx & 7;
        cpa16(sb + V_OFF + buf * 32768 + swz(c * 128 + ch * 16),
              vbase + (size_t)c * N_ + ch * 8);
    }
}

__global__ __launch_bounds__(256, 2)
void flash_mma(const float* __restrict__ x,
               const float* __restrict__ gamma,
               float* __restrict__ out)
{
    extern __shared__ char sm[];
    const u32 sb = smem_u32(sm);
    const int tid  = threadIdx.x;
    const int wid  = tid >> 5;
    const int lane = tid & 31;
    const int gid  = lane >> 2;
    const int qid  = lane & 3;
    const int b    = blockIdx.y;
    const int m0   = blockIdx.x * 64;

    if (tid < 64) ((float*)sm)[tid] = 0.0f;

    // preload K + tile 0 (single group)
    {
        int row = tid >> 2, ch = tid & 3;
        cpa16(sb + K_OFF + swz(row * 128 + ch * 16),
              g_k + (size_t)(b * N_ + m0 + row) * DQK_ + ch * 8);
    }
    load_qv(sb, tid, b, 0);
    CP_COMMIT;
    CP_WAIT0;
    __syncthreads();

    // persistent K A-frags
    u32 aK[2][4];
    {
        int row = (wid & 3) * 16 + (lane & 15);
#pragma unroll
        for (int ks = 0; ks < 2; ++ks) {
            u32 addr = sb + K_OFF + swz(row * 128 + (lane >> 4) * 16 + ks * 32);
            ldm_x4(addr, aK[ks][0], aK[ks][1], aK[ks][2], aK[ks][3]);
        }
    }

    float D[2][8][4];
#pragma unroll
    for (int ms = 0; ms < 2; ++ms)
#pragma unroll
        for (int cg = 0; cg < 8; ++cg)
#pragma unroll
            for (int r = 0; r < 4; ++r) D[ms][cg][r] = 0.0f;
    float rs0 = 0.0f, rs1 = 0.0f;

    for (int t = 0; t <= NT; ++t) {
        if (t > 0) {
            if (t <= NT - 1) CP_WAIT0;   // tile-t loads (issued at iter t-1) done
            __syncthreads();             // A: loads visible, P(t-1) complete
        }

        // ---- S(t) = K . Q(t)^T ----
        float S[4][4];
        if (t < NT) {
            const u32 qb = sb + Q_OFF + (t & 1) * 8192;
#pragma unroll
            for (int ns = 0; ns < 4; ++ns)
#pragma unroll
                for (int r = 0; r < 4; ++r) S[ns][r] = 0.0f;

            u32 bQ[2][2][4];
#pragma unroll
            for (int nn = 0; nn < 2; ++nn) {
                int nrow = (wid >> 2) * 32 + nn * 16 + (lane & 7) + ((lane >> 4) & 1) * 8;
#pragma unroll
                for (int ks = 0; ks < 2; ++ks) {
                    u32 addr = qb + swz(nrow * 128 + ((lane >> 3) & 1) * 16 + ks * 32);
                    ldm_x4(addr, bQ[ks][nn][0], bQ[ks][nn][1], bQ[ks][nn][2], bQ[ks][nn][3]);
                }
            }
#pragma unroll
            for (int ns = 0; ns < 4; ++ns)
#pragma unroll
                for (int ks = 0; ks < 2; ++ks)
                    mma_bf16(S[ns], aK[ks], &bQ[ks][ns >> 1][(ns & 1) * 2]);
        }

        // ---- PV(t-1): D += P(t-1) . V(t-1) ----
        if (t > 0) {
            const u32 pb = sb + P_OFF + ((t - 1) & 1) * 8192;
            const u32 vb = sb + V_OFF + ((t - 1) & 1) * 32768;
#pragma unroll
            for (int ksn = 0; ksn < 4; ++ksn) {
                u32 aP[2][4];
#pragma unroll
                for (int ms = 0; ms < 2; ++ms) {
                    int row = (wid & 1) * 32 + ms * 16 + (lane & 15);
                    u32 addr = pb + swz(row * 128 + (lane >> 4) * 16 + ksn * 32);
                    ldm_x4(addr, aP[ms][0], aP[ms][1], aP[ms][2], aP[ms][3]);
                }
                u32 bV[4][4];
#pragma unroll
                for (int pp = 0; pp < 4; ++pp) {
                    int crow = (wid >> 1) * 64 + pp * 16 + (lane & 7) + ((lane >> 4) & 1) * 8;
                    u32 addr = vb + swz(crow * 128 + ((lane >> 3) & 1) * 16 + ksn * 32);
                    ldm_x4(addr, bV[pp][0], bV[pp][1], bV[pp][2], bV[pp][3]);
                }
#pragma unroll
                for (int ms = 0; ms < 2; ++ms)
#pragma unroll
                    for (int cg = 0; cg < 8; ++cg)
                        mma_bf16(D[ms][cg], aP[ms], &bV[cg >> 1][(cg & 1) * 2]);
            }
        }

        __syncthreads();                 // B: all LDSM reads of V(t-1)/P(t-1) done

        // ---- prefetch tile t+1 (overlaps with tensor drain + exp) ----
        if (t < NT - 1) {
            load_qv(sb, tid, b, t + 1);
            CP_COMMIT;
        }

        // ---- exp(t) -> P(t) buffer; accumulate row sums ----
        if (t < NT) {
            const u32 pw = sb + P_OFF + (t & 1) * 8192;
            const int mlo = (wid & 3) * 16 + gid;
#pragma unroll
            for (int ns = 0; ns < 4; ++ns) {
                float e0, e1, e2, e3;
                asm("ex2.approx.f32 %0, %1;" : "=f"(e0) : "f"(S[ns][0]));
                asm("ex2.approx.f32 %0, %1;" : "=f"(e1) : "f"(S[ns][1]));
                asm("ex2.approx.f32 %0, %1;" : "=f"(e2) : "f"(S[ns][2]));
                asm("ex2.approx.f32 %0, %1;" : "=f"(e3) : "f"(S[ns][3]));
                rs0 += e0 + e1;
                rs1 += e2 + e3;
                int n = (wid >> 2) * 32 + ns * 8 + 2 * qid;
                *(u32*)(pw - sb + (size_t)sm + swz(mlo * 128 + n * 2))       = pack_bf16x2(e0, e1);
                *(u32*)(pw - sb + (size_t)sm + swz((mlo + 8) * 128 + n * 2)) = pack_bf16x2(e2, e3);
            }
        }
    }

    // ---- row sums: 4-lane reduce + cross-warp atomic ----
    __syncthreads();
    rs0 += __shfl_xor_sync(0xffffffffu, rs0, 1);
    rs0 += __shfl_xor_sync(0xffffffffu, rs0, 2);
    rs1 += __shfl_xor_sync(0xffffffffu, rs1, 1);
    rs1 += __shfl_xor_sync(0xffffffffu, rs1, 2);
    if (qid == 0) {
        atomicAdd(&((float*)sm)[(wid & 3) * 16 + gid],     rs0);
        atomicAdd(&((float*)sm)[(wid & 3) * 16 + gid + 8], rs1);
    }
    __syncthreads();

    // ---- stage normalized D as [c][m] for coalesced epilogue ----
    float* stage = (float*)(sm + STAGE_OFF);
#pragma unroll
    for (int ms = 0; ms < 2; ++ms) {
        int r0 = (wid & 1) * 32 + ms * 16 + gid;
        int r1 = r0 + 8;
        float i0 = 1.0f / ((float*)sm)[r0];
        float i1 = 1.0f / ((float*)sm)[r1];
#pragma unroll
        for (int cg = 0; cg < 8; ++cg) {
            int c = (wid >> 1) * 64 + cg * 8 + 2 * qid;
            stage[c * 66 + r0]       = D[ms][cg][0] * i0;
            stage[(c + 1) * 66 + r0] = D[ms][cg][1] * i0;
            stage[c * 66 + r1]       = D[ms][cg][2] * i1;
            stage[(c + 1) * 66 + r1] = D[ms][cg][3] * i1;
        }
    }
    __syncthreads();

    const float g = gamma[0];
#pragma unroll 4
    for (int i = 0; i < 64; ++i) {
        int m = tid & 63;
        int c = (tid >> 6) + 4 * i;
        size_t ga = ((size_t)(b * C_ + c)) * N_ + m0 + m;
        out[ga] = g * stage[c * 66 + m] + x[ga];
    }
}

// =============================================================================
// launcher
// =============================================================================
extern "C" void kernel_launch(void* const* d_in, const int* in_sizes, int n_in,
                              void* d_out, int out_size)
{
    const float* x     = (const float*)d_in[0];
    const float* Wq    = (const float*)d_in[1];
    const float* bq    = (const float*)d_in[2];
    const float* Wk    = (const float*)d_in[3];
    const float* bk    = (const float*)d_in[4];
    const float* Wv    = (const float*)d_in[5];
    const float* bv    = (const float*)d_in[6];
    const float* gamma = (const float*)d_in[7];
    float* out = (float*)d_out;

    (void)cudaFuncSetAttribute(proj_gemm,
                               cudaFuncAttributeMaxDynamicSharedMemorySize, SMEM_P);
    (void)cudaFuncSetAttribute(flash_mma,
                               cudaFuncAttributeMaxDynamicSharedMemorySize, SMEM_F);

    wconv<<<320, 256>>>(Wq, bq, Wk, bk, Wv, bv);
    xT_kernel<<<dim3(N_ / 64, C_ / 64, B_), 256>>>(x);
    proj_gemm<<<dim3(N_ / 128, 5, B_), 128, SMEM_P>>>();
    flash_mma<<<dim3(N_ / 64, B_), 256, SMEM_F>>>(x, gamma, out);
}